// round 9
// baseline (speedup 1.0000x reference)
#include <cuda_runtime.h>
#include <math.h>
#include <stdint.h>

#define Bn   512
#define Nn   199
#define Hn   4
#define Fn   64
#define Un   64
#define OUTC 455           // H*U + N
#define MT   13            // m16 tiles covering 200 rows (208)
#define KT   25            // k/j tiles of 8 covering 200
#define FT   8             // f/u tiles of 8 (64)
#define THREADS 256
#define XST  200           // XsT row stride (== 8 mod 32: conflict-free float2)

// Preprocessed operand banks (global, L2-resident)
__device__ float g_Ga[Hn * MT * KT * 32 * 4];  // feat A-frags: G[m][n] tf32
__device__ float g_Kb[Hn * KT * FT * 32 * 2];  // dense B-frags: K[f][j] tf32
__device__ float g_Fb[Hn * FT * FT * 32 * 2];  // fc B-frags: fc[f][u] tf32
__device__ float g_Ac[MT * KT * 32 * 4];       // adjacency in C-frag layout

__device__ __forceinline__ float tf32r(float x) {
    asm("cvt.rna.tf32.f32 %0, %0;" : "+f"(x)); return x;
}
__device__ __forceinline__ void mma_tf32(float c[4], const uint32_t a[4],
                                         uint32_t b0, uint32_t b1) {
    asm volatile(
        "mma.sync.aligned.m16n8k8.row.col.f32.tf32.tf32.f32 "
        "{%0,%1,%2,%3}, {%4,%5,%6,%7}, {%8,%9}, {%0,%1,%2,%3};"
        : "+f"(c[0]), "+f"(c[1]), "+f"(c[2]), "+f"(c[3])
        : "r"(a[0]), "r"(a[1]), "r"(a[2]), "r"(a[3]), "r"(b0), "r"(b1));
}
// C-fragment (r,2c even/odd pairs) -> A-fragment (r,k) of the same 8-wide tile
__device__ __forceinline__ void c2a(const float c[4], float a[4], int lane) {
    int s0 = (lane & ~3) | ((lane & 3) >> 1);
    int s1 = s0 + 2;
    float v0 = __shfl_sync(~0u, c[0], s0), v1 = __shfl_sync(~0u, c[1], s0);
    float v2 = __shfl_sync(~0u, c[2], s0), v3 = __shfl_sync(~0u, c[3], s0);
    float w0 = __shfl_sync(~0u, c[0], s1), w1 = __shfl_sync(~0u, c[1], s1);
    float w2 = __shfl_sync(~0u, c[2], s1), w3 = __shfl_sync(~0u, c[3], s1);
    bool odd = lane & 1;
    a[0] = odd ? v1 : v0;  a[1] = odd ? v3 : v2;
    a[2] = odd ? w1 : w0;  a[3] = odd ? w3 : w2;
}

// ---------------- operand prep kernels ----------------
__global__ void prep_ga(const float* __restrict__ A, const float* __restrict__ P) {
    int t = blockIdx.x * blockDim.x + threadIdx.x;
    if (t >= Hn * MT * KT * 128) return;
    int i = t & 3, lane = (t >> 2) & 31, rest = t >> 7;
    int kt = rest % KT; rest /= KT;
    int mt = rest % MT; int h = rest / MT;
    int row = (lane >> 2) + (i & 1) * 8;
    int kc  = (lane & 3) + ((i >> 1) << 2);
    int m = 16 * mt + row, n = 8 * kt + kc;
    float v = 0.f;
    if (m < Nn && n < Nn) v = tf32r(A[n * Nn + m] * P[(h * Nn + n) * Nn + m]);
    g_Ga[t] = v;
}
__global__ void prep_kb(const float* __restrict__ KER) {
    int t = blockIdx.x * blockDim.x + threadIdx.x;
    if (t >= Hn * KT * FT * 64) return;
    int i = t & 1, lane = (t >> 1) & 31, rest = t >> 6;
    int kt = rest & 7; rest >>= 3;
    int jt = rest % KT; int h = rest / KT;
    int f = 8 * kt + (lane & 3) + 4 * i;
    int j = 8 * jt + (lane >> 2);
    g_Kb[t] = (j < Nn) ? tf32r(KER[(h * Fn + f) * Nn + j]) : 0.f;
}
__global__ void prep_fb(const float* __restrict__ FC) {
    int t = blockIdx.x * blockDim.x + threadIdx.x;
    if (t >= Hn * FT * FT * 64) return;
    int i = t & 1, lane = (t >> 1) & 31, rest = t >> 6;
    int kt = rest & 7; rest >>= 3;
    int ut = rest & 7; int h = rest >> 3;
    int f = 8 * kt + (lane & 3) + 4 * i;
    int u = 8 * ut + (lane >> 2);
    g_Fb[t] = tf32r(FC[(h * Fn + f) * Un + u]);
}
__global__ void prep_ac(const float* __restrict__ A) {
    int t = blockIdx.x * blockDim.x + threadIdx.x;
    if (t >= MT * KT * 128) return;
    int i = t & 3, lane = (t >> 2) & 31, rest = t >> 7;
    int jt = rest % KT; int mt = rest / KT;
    int r = (lane >> 2) + (i >> 1) * 8;
    int j = 8 * jt + 2 * (lane & 3) + (i & 1);
    int m = 16 * mt + r;
    g_Ac[t] = (m < Nn && j < Nn) ? A[m * Nn + j] : 0.f;
}

// ---------------- main fused kernel ----------------
// grid: Bn*Hn*2 blocks; each block handles half the m-tiles of one (b,h).
__global__ __launch_bounds__(THREADS, 2)
void gc_kernel(const float* __restrict__ X, const float* __restrict__ B1,
               const float* __restrict__ B2, float* __restrict__ out)
{
    extern __shared__ float smem[];
    float* XsT = smem;                 // [64][XST] tf32 X^T, pair-permuted cols
    float* b1s = XsT + Fn * XST;       // [200]
    float* b2s = b1s + 200;            // [64]

    const int half = blockIdx.x & 1;
    const int h = (blockIdx.x >> 1) & (Hn - 1);
    const int b = blockIdx.x >> 3;
    const int tid = threadIdx.x;
    const int w = tid >> 5;
    const int lane = tid & 31;
    const bool last_h = (h == Hn - 1);

    for (int i = tid; i < 200 * Fn; i += THREADS) {
        int n = i >> 6, f = i & 63;
        float v = (n < Nn) ? X[((size_t)b * Nn + n) * Fn + f] : 0.f;
        // pair permutation: slot pair 2c holds (n=c, n=c+4) of each 8-tile
        int col = (n & ~7) | ((n & 3) << 1) | ((n >> 2) & 1);
        XsT[f * XST + col] = tf32r(v);
    }
    for (int i = tid; i < 200; i += THREADS) b1s[i] = (i < Nn) ? B1[h * Nn + i] : 0.f;
    if (tid < Un) b2s[tid] = B2[h * Un + tid];
    __syncthreads();

    const int wg = (half ? 7 : 0) + w;        // global m-tile index
    if (wg >= (half ? MT : 7)) return;        // 1-2 idle warps per half
    const int m0 = 16 * wg;
    const int mA = m0 + (lane >> 2);          // row for c0/c1
    const int mB = mA + 8;                    // row for c2/c3
    const int pairOff = 2 * (lane & 3);       // pair slot within tile
    const int bRow = (lane >> 2);             // n-dim row within B tile

    // ======== FEAT: fC[ft] = G(m-tile) @ X  (k = 200 nodes) ========
    float fC[FT][4];
    #pragma unroll
    for (int t = 0; t < FT; t++) { fC[t][0]=fC[t][1]=fC[t][2]=fC[t][3]=0.f; }
    {
        const float4* gaP = ((const float4*)g_Ga) + ((size_t)(h * MT + wg) * KT) * 32 + lane;
        float4 ga = __ldg(gaP);
        #pragma unroll 1
        for (int kt = 0; kt < KT; kt++) {
            float4 gan = (kt + 1 < KT) ? __ldg(gaP + (kt + 1) * 32) : ga;
            uint32_t a[4] = { __float_as_uint(ga.x), __float_as_uint(ga.y),
                              __float_as_uint(ga.z), __float_as_uint(ga.w) };
            #pragma unroll
            for (int ft = 0; ft < FT; ft++) {
                float2 xv = *(const float2*)&XsT[(8 * ft + bRow) * XST + 8 * kt + pairOff];
                mma_tf32(fC[ft], a, __float_as_uint(xv.x), __float_as_uint(xv.y));
            }
            ga = gan;
        }
    }
    // permute feat C -> A fragments (k = f)
    uint32_t fA[FT][4];
    #pragma unroll
    for (int t = 0; t < FT; t++) {
        float a4[4]; c2a(fC[t], a4, lane);
        #pragma unroll
        for (int q = 0; q < 4; q++) fA[t][q] = __float_as_uint(tf32r(a4[q]));
    }

    // ======== DENSE + masked exp + NODE (fused over j-tiles) ========
    float nC[FT][4];
    #pragma unroll
    for (int t = 0; t < FT; t++) { nC[t][0]=nC[t][1]=nC[t][2]=nC[t][3]=0.f; }
    float s0 = 0.f, s1 = 0.f;

    const float2* kbP = ((const float2*)g_Kb) + ((size_t)h * KT * FT) * 32 + lane;
    const float4* acP = ((const float4*)g_Ac) + ((size_t)wg * KT) * 32 + lane;

    float2 kb[FT]; float4 ac;
    #pragma unroll
    for (int kt = 0; kt < FT; kt++) kb[kt] = __ldg(kbP + kt * 32);
    ac = __ldg(acP);

    #pragma unroll 1
    for (int jt = 0; jt < KT; jt++) {
        float2 kbn[FT]; float4 acn;
        if (jt + 1 < KT) {
            #pragma unroll
            for (int kt = 0; kt < FT; kt++)
                kbn[kt] = __ldg(kbP + ((jt + 1) * FT + kt) * 32);
            acn = __ldg(acP + (jt + 1) * 32);
        } else {
            #pragma unroll
            for (int kt = 0; kt < FT; kt++) kbn[kt] = kb[kt];
            acn = ac;
        }

        // dual accumulators: halve the serial HMMA dependency chain
        float dC0[4] = {0.f, 0.f, 0.f, 0.f};
        float dC1[4] = {0.f, 0.f, 0.f, 0.f};
        #pragma unroll
        for (int kt = 0; kt < FT; kt += 2) {
            mma_tf32(dC0, fA[kt],     __float_as_uint(kb[kt].x),     __float_as_uint(kb[kt].y));
            mma_tf32(dC1, fA[kt + 1], __float_as_uint(kb[kt + 1].x), __float_as_uint(kb[kt + 1].y));
        }

        int j = 8 * jt + 2 * (lane & 3);
        float2 b1v = *(const float2*)&b1s[j];
        float e0 = ac.x * __expf(dC0[0] + dC1[0] + b1v.x);
        float e1 = ac.y * __expf(dC0[1] + dC1[1] + b1v.y);
        float e2 = ac.z * __expf(dC0[2] + dC1[2] + b1v.x);
        float e3 = ac.w * __expf(dC0[3] + dC1[3] + b1v.y);
        s0 += e0 + e1; s1 += e2 + e3;

        if (last_h) {   // raw (unnormalized) mask; rescaled by same thread later
            if (mA < Nn) {
                float* o = out + ((size_t)b * Nn + mA) * OUTC + Hn * Un + j;
                o[0] = e0; if (j < 198) o[1] = e1;
            }
            if (mB < Nn) {
                float* o = out + ((size_t)b * Nn + mB) * OUTC + Hn * Un + j;
                o[0] = e2; if (j < 198) o[1] = e3;
            }
        }
        // node += e-tile @ X (k = this j-tile)
        float ec[4] = {e0, e1, e2, e3}, ea[4];
        c2a(ec, ea, lane);
        uint32_t eA[4];
        #pragma unroll
        for (int q = 0; q < 4; q++) eA[q] = __float_as_uint(tf32r(ea[q]));
        #pragma unroll
        for (int ft = 0; ft < FT; ft++) {
            float2 xv = *(const float2*)&XsT[(8 * ft + bRow) * XST + 8 * jt + pairOff];
            mma_tf32(nC[ft], eA, __float_as_uint(xv.x), __float_as_uint(xv.y));
        }
        #pragma unroll
        for (int kt = 0; kt < FT; kt++) kb[kt] = kbn[kt];
        ac = acn;
    }
    // row sums across the 4 lanes of each row group
    s0 += __shfl_xor_sync(~0u, s0, 1); s0 += __shfl_xor_sync(~0u, s0, 2);
    s1 += __shfl_xor_sync(~0u, s1, 1); s1 += __shfl_xor_sync(~0u, s1, 2);
    float inv0 = 1.f / s0, inv1 = 1.f / s1;

    if (last_h) {   // normalize mask in-place (same thread wrote these)
        #pragma unroll 1
        for (int jt = 0; jt < KT; jt++) {
            int j = 8 * jt + 2 * (lane & 3);
            if (mA < Nn) {
                float* o = out + ((size_t)b * Nn + mA) * OUTC + Hn * Un + j;
                o[0] *= inv0; if (j < 198) o[1] *= inv0;
            }
            if (mB < Nn) {
                float* o = out + ((size_t)b * Nn + mB) * OUTC + Hn * Un + j;
                o[0] *= inv1; if (j < 198) o[1] *= inv1;
            }
        }
    }
    // normalize node accumulators
    #pragma unroll
    for (int t = 0; t < FT; t++) {
        nC[t][0] *= inv0; nC[t][1] *= inv0;
        nC[t][2] *= inv1; nC[t][3] *= inv1;
    }
    // permute node C -> A fragments (k = f)
    uint32_t nA[FT][4];
    #pragma unroll
    for (int t = 0; t < FT; t++) {
        float a4[4]; c2a(nC[t], a4, lane);
        #pragma unroll
        for (int q = 0; q < 4; q++) nA[t][q] = __float_as_uint(tf32r(a4[q]));
    }

    // ======== FC: out = node @ fc + b2 ========
    const float2* fbP = ((const float2*)g_Fb) + ((size_t)h * FT * FT) * 32 + lane;
    #pragma unroll 1
    for (int ut = 0; ut < FT; ut++) {
        float oC[4] = {0.f, 0.f, 0.f, 0.f};
        #pragma unroll
        for (int kt = 0; kt < FT; kt++) {
            float2 fb = __ldg(fbP + (ut * FT + kt) * 32);
            mma_tf32(oC, nA[kt], __float_as_uint(fb.x), __float_as_uint(fb.y));
        }
        int u = 8 * ut + 2 * (lane & 3);
        float2 b2v = *(const float2*)&b2s[u];
        if (mA < Nn) {
            float* o = out + ((size_t)b * Nn + mA) * OUTC + h * Un + u;
            o[0] = oC[0] + b2v.x; o[1] = oC[1] + b2v.y;
        }
        if (mB < Nn) {
            float* o = out + ((size_t)b * Nn + mB) * OUTC + h * Un + u;
            o[0] = oC[2] + b2v.x; o[1] = oC[3] + b2v.y;
        }
    }
}

static const size_t SMEM_BYTES = (size_t)(Fn * XST + 200 + Un) * 4;

extern "C" void kernel_launch(void* const* d_in, const int* in_sizes, int n_in,
                              void* d_out, int out_size) {
    const float* X   = (const float*)d_in[0];
    const float* A   = (const float*)d_in[1];
    const float* KER = (const float*)d_in[2];
    const float* P   = (const float*)d_in[3];
    const float* FC  = (const float*)d_in[4];
    const float* B1  = (const float*)d_in[5];
    const float* B2  = (const float*)d_in[6];
    float* out = (float*)d_out;

    prep_ga<<<(Hn * MT * KT * 128 + 255) / 256, 256>>>(A, P);
    prep_kb<<<(Hn * KT * FT * 64 + 255) / 256, 256>>>(KER);
    prep_fb<<<(Hn * FT * FT * 64 + 255) / 256, 256>>>(FC);
    prep_ac<<<(MT * KT * 128 + 255) / 256, 256>>>(A);

    cudaFuncSetAttribute(gc_kernel, cudaFuncAttributeMaxDynamicSharedMemorySize,
                         (int)SMEM_BYTES);
    gc_kernel<<<Bn * Hn * 2, THREADS, SMEM_BYTES>>>(X, B1, B2, out);
}